// round 1
// baseline (speedup 1.0000x reference)
#include <cuda_runtime.h>
#include <math.h>

#define BATCH 4
#define SEQ   2048
#define DIMN  1024
#define HEADS 16
#define DHEAD 64
#define ROWS  (BATCH*SEQ)      /* 8192 */
#define QKV_N (3*DIMN)         /* 3072 */
#define FPAD  68               /* 64 + 4 pad for smem tiles */

// Scratch (allocation-free rule: __device__ globals)
static __device__ float g_xn[(size_t)ROWS*DIMN];     // 32 MB
static __device__ float g_qkv[(size_t)ROWS*QKV_N];   // 96 MB
static __device__ float g_attn[(size_t)ROWS*DIMN];   // 32 MB

// ---------------------------------------------------------------------------
// LayerNorm: one block per row of 1024
// ---------------------------------------------------------------------------
__global__ __launch_bounds__(256) void ln_kernel(const float* __restrict__ x,
                                                 const float* __restrict__ gamma,
                                                 const float* __restrict__ beta)
{
    __shared__ float red[16];
    const int row = blockIdx.x;
    const int t = threadIdx.x;
    const float* xr = x + (size_t)row * DIMN;
    float4 v = *(const float4*)(xr + t * 4);
    float s = v.x + v.y + v.z + v.w;
    float q = v.x*v.x + v.y*v.y + v.z*v.z + v.w*v.w;
    #pragma unroll
    for (int o = 16; o; o >>= 1) {
        s += __shfl_xor_sync(0xffffffffu, s, o);
        q += __shfl_xor_sync(0xffffffffu, q, o);
    }
    if ((t & 31) == 0) { red[t >> 5] = s; red[8 + (t >> 5)] = q; }
    __syncthreads();
    if (t < 32) {
        float ss = (t < 8) ? red[t] : 0.f;
        float qq = (t < 8) ? red[8 + t] : 0.f;
        #pragma unroll
        for (int o = 4; o; o >>= 1) {
            ss += __shfl_xor_sync(0xffffffffu, ss, o);
            qq += __shfl_xor_sync(0xffffffffu, qq, o);
        }
        if (t == 0) { red[0] = ss; red[1] = qq; }
    }
    __syncthreads();
    const float mean = red[0] * (1.f / DIMN);
    const float var  = red[1] * (1.f / DIMN) - mean * mean;
    const float inv  = rsqrtf(var + 1e-5f);
    float4 g = *(const float4*)(gamma + t * 4);
    float4 b = *(const float4*)(beta  + t * 4);
    float4 o4;
    o4.x = (v.x - mean) * inv * g.x + b.x;
    o4.y = (v.y - mean) * inv * g.y + b.y;
    o4.z = (v.z - mean) * inv * g.z + b.z;
    o4.w = (v.w - mean) * inv * g.w + b.w;
    *(float4*)(g_xn + (size_t)row * DIMN + t * 4) = o4;
}

// ---------------------------------------------------------------------------
// SIMT fp32 GEMM: C[M,N] = A[M,K] @ B[K,N] (+bias). 128x128x16 tile, 8x8/thread.
// M,N multiples of 128; K multiple of 16.
// ---------------------------------------------------------------------------
__global__ __launch_bounds__(256) void gemm_kernel(const float* __restrict__ A,
                                                   const float* __restrict__ B,
                                                   const float* __restrict__ bias,
                                                   float* __restrict__ C,
                                                   int M, int N, int K)
{
    __shared__ float As[16][132];
    __shared__ float Bs[16][132];
    const int tid = threadIdx.x;
    const int tx = tid & 15, ty = tid >> 4;
    const int bm = blockIdx.y * 128, bn = blockIdx.x * 128;

    float acc[8][8] = {};

    for (int k0 = 0; k0 < K; k0 += 16) {
        #pragma unroll
        for (int p = 0; p < 2; p++) {
            int idx = tid + p * 256;
            int row = idx >> 2, c4 = (idx & 3) * 4;
            float4 va = *(const float4*)(A + (size_t)(bm + row) * K + k0 + c4);
            As[c4 + 0][row] = va.x; As[c4 + 1][row] = va.y;
            As[c4 + 2][row] = va.z; As[c4 + 3][row] = va.w;
            int kr = idx >> 5, c = (idx & 31) * 4;
            *(float4*)&Bs[kr][c] = *(const float4*)(B + (size_t)(k0 + kr) * N + bn + c);
        }
        __syncthreads();
        #pragma unroll
        for (int k = 0; k < 16; k++) {
            float4 a0 = *(float4*)&As[k][ty * 8];
            float4 a1 = *(float4*)&As[k][ty * 8 + 4];
            float4 b0 = *(float4*)&Bs[k][tx * 8];
            float4 b1 = *(float4*)&Bs[k][tx * 8 + 4];
            float a[8] = {a0.x, a0.y, a0.z, a0.w, a1.x, a1.y, a1.z, a1.w};
            float b[8] = {b0.x, b0.y, b0.z, b0.w, b1.x, b1.y, b1.z, b1.w};
            #pragma unroll
            for (int i = 0; i < 8; i++)
                #pragma unroll
                for (int j = 0; j < 8; j++)
                    acc[i][j] += a[i] * b[j];
        }
        __syncthreads();
    }

    float bb[8];
    #pragma unroll
    for (int j = 0; j < 8; j++)
        bb[j] = bias ? bias[bn + tx * 8 + j] : 0.f;

    #pragma unroll
    for (int i = 0; i < 8; i++) {
        size_t off = (size_t)(bm + ty * 8 + i) * N + bn + tx * 8;
        float4 o0, o1;
        o0.x = acc[i][0] + bb[0]; o0.y = acc[i][1] + bb[1];
        o0.z = acc[i][2] + bb[2]; o0.w = acc[i][3] + bb[3];
        o1.x = acc[i][4] + bb[4]; o1.y = acc[i][5] + bb[5];
        o1.z = acc[i][6] + bb[6]; o1.w = acc[i][7] + bb[7];
        *(float4*)(C + off)     = o0;
        *(float4*)(C + off + 4) = o1;
    }
}

// ---------------------------------------------------------------------------
// Flash attention fp32: per (b,h), BM=64 query rows per block, BN=64 kv tile.
// q/k/v live interleaved in g_qkv [8192, 3072].
// ---------------------------------------------------------------------------
__global__ __launch_bounds__(256) void flash_kernel(const float* __restrict__ qkv,
                                                    float* __restrict__ attn)
{
    extern __shared__ float sm[];
    float* Qs = sm;                 // [d][row] transposed, pre-scaled
    float* Ks = sm + 64 * FPAD;     // [d][col] transposed
    float* Vs = sm + 2 * 64 * FPAD; // [key][d]
    float* Ps = sm + 3 * 64 * FPAD; // [key][row] transposed

    const int tid = threadIdx.x;
    const int tx = tid & 15, ty = tid >> 4;
    const int qt = blockIdx.x;          // query tile 0..31
    const int bh = blockIdx.y;          // 0..63
    const int b = bh >> 4, h = bh & 15;
    const size_t base = (size_t)b * SEQ;
    const int qoff = h * DHEAD;
    const int koff = DIMN + h * DHEAD;
    const int voff = 2 * DIMN + h * DHEAD;
    const float scale = 0.125f;         // 64^-0.5

    // Load Q tile (transposed, pre-scaled)
    #pragma unroll
    for (int p = 0; p < 4; p++) {
        int idx = tid + p * 256;
        int row = idx >> 4, c4 = (idx & 15) * 4;
        float4 v = *(const float4*)(qkv + (base + qt * 64 + row) * QKV_N + qoff + c4);
        Qs[(c4 + 0) * FPAD + row] = v.x * scale;
        Qs[(c4 + 1) * FPAD + row] = v.y * scale;
        Qs[(c4 + 2) * FPAD + row] = v.z * scale;
        Qs[(c4 + 3) * FPAD + row] = v.w * scale;
    }

    const float NEG_INF = __int_as_float(0xff800000);
    float m_prev[4] = {NEG_INF, NEG_INF, NEG_INF, NEG_INF};
    float l[4] = {0.f, 0.f, 0.f, 0.f};
    float o[4][4] = {};

    for (int kt = 0; kt < SEQ / 64; kt++) {
        __syncthreads();  // protect K/V/P smem reuse (and first-iter Q visibility)
        #pragma unroll
        for (int p = 0; p < 4; p++) {
            int idx = tid + p * 256;
            int row = idx >> 4, c4 = (idx & 15) * 4;
            const float* rp = qkv + (base + kt * 64 + row) * QKV_N;
            float4 kv = *(const float4*)(rp + koff + c4);
            Ks[(c4 + 0) * FPAD + row] = kv.x;
            Ks[(c4 + 1) * FPAD + row] = kv.y;
            Ks[(c4 + 2) * FPAD + row] = kv.z;
            Ks[(c4 + 3) * FPAD + row] = kv.w;
            *(float4*)&Vs[row * FPAD + c4] = *(const float4*)(rp + voff + c4);
        }
        __syncthreads();

        // S = (Q*scale) @ K^T for this thread's 4x4 micro-tile
        float s4[4][4] = {};
        #pragma unroll 8
        for (int k = 0; k < 64; k++) {
            float4 a  = *(float4*)&Qs[k * FPAD + ty * 4];
            float4 bq = *(float4*)&Ks[k * FPAD + tx * 4];
            s4[0][0] += a.x * bq.x; s4[0][1] += a.x * bq.y; s4[0][2] += a.x * bq.z; s4[0][3] += a.x * bq.w;
            s4[1][0] += a.y * bq.x; s4[1][1] += a.y * bq.y; s4[1][2] += a.y * bq.z; s4[1][3] += a.y * bq.w;
            s4[2][0] += a.z * bq.x; s4[2][1] += a.z * bq.y; s4[2][2] += a.z * bq.z; s4[2][3] += a.z * bq.w;
            s4[3][0] += a.w * bq.x; s4[3][1] += a.w * bq.y; s4[3][2] += a.w * bq.z; s4[3][3] += a.w * bq.w;
        }

        // online softmax (reduce across the 16 tx-lanes that share each row)
        #pragma unroll
        for (int i = 0; i < 4; i++) {
            float mt = fmaxf(fmaxf(s4[i][0], s4[i][1]), fmaxf(s4[i][2], s4[i][3]));
            mt = fmaxf(mt, __shfl_xor_sync(0xffffffffu, mt, 1));
            mt = fmaxf(mt, __shfl_xor_sync(0xffffffffu, mt, 2));
            mt = fmaxf(mt, __shfl_xor_sync(0xffffffffu, mt, 4));
            mt = fmaxf(mt, __shfl_xor_sync(0xffffffffu, mt, 8));
            float mn = fmaxf(m_prev[i], mt);
            float f = __expf(m_prev[i] - mn);   // -inf -> 0 on first tile
            float rs = 0.f;
            #pragma unroll
            for (int j = 0; j < 4; j++) {
                float pv = __expf(s4[i][j] - mn);
                s4[i][j] = pv;
                rs += pv;
            }
            rs += __shfl_xor_sync(0xffffffffu, rs, 1);
            rs += __shfl_xor_sync(0xffffffffu, rs, 2);
            rs += __shfl_xor_sync(0xffffffffu, rs, 4);
            rs += __shfl_xor_sync(0xffffffffu, rs, 8);
            l[i] = l[i] * f + rs;
            m_prev[i] = mn;
            #pragma unroll
            for (int j = 0; j < 4; j++) o[i][j] *= f;
        }

        // stash P transposed for the PV GEMM
        #pragma unroll
        for (int i = 0; i < 4; i++)
            #pragma unroll
            for (int j = 0; j < 4; j++)
                Ps[(tx * 4 + j) * FPAD + ty * 4 + i] = s4[i][j];
        __syncthreads();

        // O += P @ V
        #pragma unroll 8
        for (int k = 0; k < 64; k++) {
            float4 pp = *(float4*)&Ps[k * FPAD + ty * 4];
            float4 vv = *(float4*)&Vs[k * FPAD + tx * 4];
            o[0][0] += pp.x * vv.x; o[0][1] += pp.x * vv.y; o[0][2] += pp.x * vv.z; o[0][3] += pp.x * vv.w;
            o[1][0] += pp.y * vv.x; o[1][1] += pp.y * vv.y; o[1][2] += pp.y * vv.z; o[1][3] += pp.y * vv.w;
            o[2][0] += pp.z * vv.x; o[2][1] += pp.z * vv.y; o[2][2] += pp.z * vv.z; o[2][3] += pp.z * vv.w;
            o[3][0] += pp.w * vv.x; o[3][1] += pp.w * vv.y; o[3][2] += pp.w * vv.z; o[3][3] += pp.w * vv.w;
        }
    }

    #pragma unroll
    for (int i = 0; i < 4; i++) {
        float inv = 1.f / l[i];
        size_t off = (base + qt * 64 + ty * 4 + i) * DIMN + h * DHEAD + tx * 4;
        float4 w;
        w.x = o[i][0] * inv; w.y = o[i][1] * inv;
        w.z = o[i][2] * inv; w.w = o[i][3] * inv;
        *(float4*)(attn + off) = w;
    }
}

// ---------------------------------------------------------------------------
extern "C" void kernel_launch(void* const* d_in, const int* in_sizes, int n_in,
                              void* d_out, int out_size)
{
    const float* x      = (const float*)d_in[0];
    const float* gamma  = (const float*)d_in[1];
    const float* beta   = (const float*)d_in[2];
    const float* w_qkv  = (const float*)d_in[3];
    const float* w_out  = (const float*)d_in[4];
    const float* b_out  = (const float*)d_in[5];
    float* out = (float*)d_out;

    float *xn, *qkvp, *attnp;
    cudaGetSymbolAddress((void**)&xn,    g_xn);
    cudaGetSymbolAddress((void**)&qkvp,  g_qkv);
    cudaGetSymbolAddress((void**)&attnp, g_attn);

    const int flash_smem = 4 * 64 * FPAD * sizeof(float);  // ~69.6 KB
    cudaFuncSetAttribute(flash_kernel, cudaFuncAttributeMaxDynamicSharedMemorySize, flash_smem);

    ln_kernel<<<ROWS, 256>>>(x, gamma, beta);
    gemm_kernel<<<dim3(QKV_N / 128, ROWS / 128), 256>>>(xn, w_qkv, nullptr, qkvp,
                                                        ROWS, QKV_N, DIMN);
    flash_kernel<<<dim3(SEQ / 64, BATCH * HEADS), 256, flash_smem>>>(qkvp, attnp);
    gemm_kernel<<<dim3(DIMN / 128, ROWS / 128), 256>>>(attnp, w_out, b_out, out,
                                                       ROWS, DIMN, DIMN);
}

// round 4
// speedup vs baseline: 2.9991x; 2.9991x over previous
#include <cuda_runtime.h>
#include <math.h>

#define BATCH 4
#define SEQ   2048
#define DIMN  1024
#define HEADS 16
#define DHEAD 64
#define ROWS  (BATCH*SEQ)      /* 8192 */
#define QKV_N (3*DIMN)         /* 3072 */

// Scratch (allocation-free rule: __device__ globals)
static __device__ float g_xn[(size_t)ROWS*DIMN];      // LN out (tf32-rounded)
static __device__ float g_qkv[(size_t)ROWS*QKV_N];    // QKV (fp32)
static __device__ float g_attn[(size_t)ROWS*DIMN];    // attn out (tf32-rounded)
static __device__ float g_wq[(size_t)DIMN*QKV_N];     // tf32-rounded w_qkv
static __device__ float g_wo[(size_t)DIMN*DIMN];      // tf32-rounded w_out

// ---------------------------------------------------------------------------
__device__ __forceinline__ unsigned f2tf(float x) {
    unsigned r;
    asm("cvt.rna.tf32.f32 %0, %1;" : "=r"(r) : "f"(x));
    return r;
}

// fast exp on the FMA pipe (x <= 0), rel err ~3e-6
__device__ __forceinline__ float fexp(float x) {
    x = fmaxf(x, -80.f);
    float y = fmaf(x, 1.4426950408889634f, 12582912.f);
    int   ni = __float_as_int(y) - 0x4B400000;
    float n = (float)ni;
    float f = fmaf(x, 1.4426950408889634f, -n);
    float p = 1.3333558146428443e-3f;
    p = fmaf(p, f, 9.6181291976353954e-3f);
    p = fmaf(p, f, 5.5504108664821580e-2f);
    p = fmaf(p, f, 2.4022650695910071e-1f);
    p = fmaf(p, f, 6.9314718055994531e-1f);
    p = fmaf(p, f, 1.0f);
    return __int_as_float((ni + 127) << 23) * p;
}

__device__ __forceinline__ void mma_tf32(float& c0, float& c1, float& c2, float& c3,
                                         unsigned a0, unsigned a1, unsigned a2, unsigned a3,
                                         unsigned b0, unsigned b1) {
    asm volatile(
        "mma.sync.aligned.m16n8k8.row.col.f32.tf32.tf32.f32 "
        "{%0,%1,%2,%3}, {%4,%5,%6,%7}, {%8,%9}, {%0,%1,%2,%3};\n"
        : "+f"(c0), "+f"(c1), "+f"(c2), "+f"(c3)
        : "r"(a0), "r"(a1), "r"(a2), "r"(a3), "r"(b0), "r"(b1));
}

#define CP_ASYNC16(dst, src) \
    asm volatile("cp.async.cg.shared.global [%0], [%1], 16;\n" :: "r"(dst), "l"(src))

// ---------------------------------------------------------------------------
// Convert a float array to tf32-rounded copy
// ---------------------------------------------------------------------------
__global__ __launch_bounds__(256) void cvt_kernel(const float* __restrict__ src,
                                                  float* __restrict__ dst, int n4) {
    int i = blockIdx.x * 256 + threadIdx.x;
    if (i < n4) {
        float4 v = ((const float4*)src)[i];
        uint4 o;
        o.x = f2tf(v.x); o.y = f2tf(v.y); o.z = f2tf(v.z); o.w = f2tf(v.w);
        ((uint4*)dst)[i] = o;
    }
}

// ---------------------------------------------------------------------------
// LayerNorm: one block per row; output tf32-rounded
// ---------------------------------------------------------------------------
__global__ __launch_bounds__(256) void ln_kernel(const float* __restrict__ x,
                                                 const float* __restrict__ gamma,
                                                 const float* __restrict__ beta) {
    __shared__ float red[16];
    const int row = blockIdx.x;
    const int t = threadIdx.x;
    const float* xr = x + (size_t)row * DIMN;
    float4 v = *(const float4*)(xr + t * 4);
    float s = v.x + v.y + v.z + v.w;
    float q = v.x*v.x + v.y*v.y + v.z*v.z + v.w*v.w;
    #pragma unroll
    for (int o = 16; o; o >>= 1) {
        s += __shfl_xor_sync(0xffffffffu, s, o);
        q += __shfl_xor_sync(0xffffffffu, q, o);
    }
    if ((t & 31) == 0) { red[t >> 5] = s; red[8 + (t >> 5)] = q; }
    __syncthreads();
    if (t < 32) {
        float ss = (t < 8) ? red[t] : 0.f;
        float qq = (t < 8) ? red[8 + t] : 0.f;
        #pragma unroll
        for (int o = 4; o; o >>= 1) {
            ss += __shfl_xor_sync(0xffffffffu, ss, o);
            qq += __shfl_xor_sync(0xffffffffu, qq, o);
        }
        if (t == 0) { red[0] = ss; red[1] = qq; }
    }
    __syncthreads();
    const float mean = red[0] * (1.f / DIMN);
    const float var  = red[1] * (1.f / DIMN) - mean * mean;
    const float inv  = rsqrtf(var + 1e-5f);
    float4 g = *(const float4*)(gamma + t * 4);
    float4 b = *(const float4*)(beta  + t * 4);
    uint4 o4;
    o4.x = f2tf((v.x - mean) * inv * g.x + b.x);
    o4.y = f2tf((v.y - mean) * inv * g.y + b.y);
    o4.z = f2tf((v.z - mean) * inv * g.z + b.z);
    o4.w = f2tf((v.w - mean) * inv * g.w + b.w);
    *(uint4*)(g_xn + (size_t)row * DIMN + t * 4) = o4;
}

// ---------------------------------------------------------------------------
// tf32 tensor-core GEMM: C[M,N] = A[M,K] @ B[K,N] (+bias)
// 128x128 block tile, BK=32, 256 threads, 8 warps (warp tile 32x64),
// cp.async double-buffered smem. A,B must be tf32-pre-rounded fp32.
// ---------------------------------------------------------------------------
#define ASTR 36
#define BSTR 136
#define ABUF (128*ASTR)   /* 4608 floats */
#define BBUF (32*BSTR)    /* 4352 floats */

__global__ __launch_bounds__(256) void gemm_tc(const float* __restrict__ A,
                                               const float* __restrict__ B,
                                               const float* __restrict__ bias,
                                               float* __restrict__ C,
                                               int M, int N, int K) {
    extern __shared__ float sm[];
    float* As = sm;                  // [2][128][ASTR]
    float* Bs = sm + 2 * ABUF;       // [2][32][BSTR]

    const int tid = threadIdx.x;
    const int wid = tid >> 5, lane = tid & 31;
    const int g = lane >> 2, tg = lane & 3;
    const int wm = wid >> 1, wn = wid & 1;
    const int bm = blockIdx.y * 128, bn = blockIdx.x * 128;

    float c[2][8][4] = {};

    auto loadAB = [&](int buf, int k0) {
        unsigned abase = (unsigned)__cvta_generic_to_shared(As + buf * ABUF);
        unsigned bbase = (unsigned)__cvta_generic_to_shared(Bs + buf * BBUF);
        #pragma unroll
        for (int p = 0; p < 4; p++) {
            int idx = tid + p * 256;
            int ar = idx >> 3, ac = (idx & 7) * 4;
            CP_ASYNC16(abase + (ar * ASTR + ac) * 4, A + (size_t)(bm + ar) * K + k0 + ac);
            int br = idx >> 5, bc = (idx & 31) * 4;
            CP_ASYNC16(bbase + (br * BSTR + bc) * 4, B + (size_t)(k0 + br) * N + bn + bc);
        }
    };

    const int nk = K / 32;
    loadAB(0, 0);
    asm volatile("cp.async.commit_group;\n");

    for (int kb = 0; kb < nk; kb++) {
        if (kb + 1 < nk) {
            loadAB((kb + 1) & 1, (kb + 1) * 32);
            asm volatile("cp.async.commit_group;\n");
            asm volatile("cp.async.wait_group 1;\n");
        } else {
            asm volatile("cp.async.wait_group 0;\n");
        }
        __syncthreads();

        const float* Ab = As + (kb & 1) * ABUF;
        const float* Bb = Bs + (kb & 1) * BBUF;
        #pragma unroll
        for (int ks = 0; ks < 4; ks++) {
            const int kk = ks * 8;
            unsigned a[2][4], b[8][2];
            #pragma unroll
            for (int mt = 0; mt < 2; mt++) {
                int r0 = wm * 32 + mt * 16;
                a[mt][0] = __float_as_uint(Ab[(r0 + g)     * ASTR + kk + tg]);
                a[mt][1] = __float_as_uint(Ab[(r0 + g + 8) * ASTR + kk + tg]);
                a[mt][2] = __float_as_uint(Ab[(r0 + g)     * ASTR + kk + tg + 4]);
                a[mt][3] = __float_as_uint(Ab[(r0 + g + 8) * ASTR + kk + tg + 4]);
            }
            #pragma unroll
            for (int nt = 0; nt < 8; nt++) {
                int col = wn * 64 + nt * 8 + g;
                b[nt][0] = __float_as_uint(Bb[(kk + tg)     * BSTR + col]);
                b[nt][1] = __float_as_uint(Bb[(kk + tg + 4) * BSTR + col]);
            }
            #pragma unroll
            for (int mt = 0; mt < 2; mt++)
                #pragma unroll
                for (int nt = 0; nt < 8; nt++)
                    mma_tf32(c[mt][nt][0], c[mt][nt][1], c[mt][nt][2], c[mt][nt][3],
                             a[mt][0], a[mt][1], a[mt][2], a[mt][3],
                             b[nt][0], b[nt][1]);
        }
        __syncthreads();
    }

    #pragma unroll
    for (int mt = 0; mt < 2; mt++) {
        int r0 = bm + wm * 32 + mt * 16 + g;
        #pragma unroll
        for (int nt = 0; nt < 8; nt++) {
            int col = bn + wn * 64 + nt * 8 + 2 * tg;
            float b0 = bias ? bias[col] : 0.f, b1 = bias ? bias[col + 1] : 0.f;
            *(float2*)(C + (size_t)r0 * N + col) =
                make_float2(c[mt][nt][0] + b0, c[mt][nt][1] + b1);
            *(float2*)(C + (size_t)(r0 + 8) * N + col) =
                make_float2(c[mt][nt][2] + b0, c[mt][nt][3] + b1);
        }
    }
}

// ---------------------------------------------------------------------------
// Flash attention, tf32 tensor cores. One block = 64 query rows of one (b,h).
// 4 warps, each owns 16 rows. BN=64 kv tiles, online softmax, poly exp.
// ---------------------------------------------------------------------------
#define FS 68
__global__ __launch_bounds__(128) void flash_tc(const float* __restrict__ qkv,
                                                float* __restrict__ attn) {
    extern __shared__ float sm[];
    float* Qs = sm;              // [64][FS]
    float* Ks = sm + 64 * FS;
    float* Vs = sm + 2 * 64 * FS;
    float* Ps = sm + 3 * 64 * FS;

    const int tid = threadIdx.x;
    const int wid = tid >> 5, lane = tid & 31;
    const int g = lane >> 2, tg = lane & 3;
    const int qr = wid * 16;
    const int qt = blockIdx.x;
    const int bh = blockIdx.y;
    const int b = bh >> 4, h = bh & 15;
    const size_t base = (size_t)b * SEQ;
    const int qoff = h * DHEAD;
    const int koff = DIMN + h * DHEAD;
    const int voff = 2 * DIMN + h * DHEAD;

    // Q tile: scale folded in, tf32-rounded
    #pragma unroll
    for (int p = 0; p < 8; p++) {
        int idx = tid + p * 128;
        int row = idx >> 4, c4 = (idx & 15) * 4;
        float4 v = *(const float4*)(qkv + (base + qt * 64 + row) * QKV_N + qoff + c4);
        uint4 o;
        o.x = f2tf(v.x * 0.125f); o.y = f2tf(v.y * 0.125f);
        o.z = f2tf(v.z * 0.125f); o.w = f2tf(v.w * 0.125f);
        *(uint4*)(Qs + row * FS + c4) = o;
    }

    const float NEG = -3.0e38f;
    float m[2] = {NEG, NEG}, l[2] = {0.f, 0.f};
    float o[8][4] = {};

    for (int kt = 0; kt < SEQ / 64; kt++) {
        __syncthreads();
        #pragma unroll
        for (int p = 0; p < 8; p++) {
            int idx = tid + p * 128;
            int row = idx >> 4, c4 = (idx & 15) * 4;
            const float* rp = qkv + (base + kt * 64 + row) * QKV_N;
            float4 kv = *(const float4*)(rp + koff + c4);
            float4 vv = *(const float4*)(rp + voff + c4);
            uint4 ko, vo;
            ko.x = f2tf(kv.x); ko.y = f2tf(kv.y); ko.z = f2tf(kv.z); ko.w = f2tf(kv.w);
            vo.x = f2tf(vv.x); vo.y = f2tf(vv.y); vo.z = f2tf(vv.z); vo.w = f2tf(vv.w);
            *(uint4*)(Ks + row * FS + c4) = ko;
            *(uint4*)(Vs + row * FS + c4) = vo;
        }
        __syncthreads();

        // S = Q @ K^T (16x64 per warp)
        float sc[8][4] = {};
        #pragma unroll
        for (int ks = 0; ks < 8; ks++) {
            const int kk = ks * 8;
            unsigned a0 = __float_as_uint(Qs[(qr + g)     * FS + kk + tg]);
            unsigned a1 = __float_as_uint(Qs[(qr + g + 8) * FS + kk + tg]);
            unsigned a2 = __float_as_uint(Qs[(qr + g)     * FS + kk + tg + 4]);
            unsigned a3 = __float_as_uint(Qs[(qr + g + 8) * FS + kk + tg + 4]);
            #pragma unroll
            for (int nt = 0; nt < 8; nt++) {
                unsigned b0 = __float_as_uint(Ks[(nt * 8 + g) * FS + kk + tg]);
                unsigned b1 = __float_as_uint(Ks[(nt * 8 + g) * FS + kk + tg + 4]);
                mma_tf32(sc[nt][0], sc[nt][1], sc[nt][2], sc[nt][3],
                         a0, a1, a2, a3, b0, b1);
            }
        }

        // online softmax, rows g (rh=0) and g+8 (rh=1)
        #pragma unroll
        for (int rh = 0; rh < 2; rh++) {
            float mt = NEG;
            #pragma unroll
            for (int nt = 0; nt < 8; nt++)
                mt = fmaxf(mt, fmaxf(sc[nt][2 * rh], sc[nt][2 * rh + 1]));
            mt = fmaxf(mt, __shfl_xor_sync(0xffffffffu, mt, 1));
            mt = fmaxf(mt, __shfl_xor_sync(0xffffffffu, mt, 2));
            float mn = fmaxf(m[rh], mt);
            float fs = fexp(m[rh] - mn);
            float rs = 0.f;
            int prow = (qr + g + 8 * rh) * FS;
            #pragma unroll
            for (int nt = 0; nt < 8; nt++) {
                unsigned p0 = f2tf(fexp(sc[nt][2 * rh]     - mn));
                unsigned p1 = f2tf(fexp(sc[nt][2 * rh + 1] - mn));
                rs += __uint_as_float(p0) + __uint_as_float(p1);
                *(float2*)(Ps + prow + nt * 8 + 2 * tg) =
                    make_float2(__uint_as_float(p0), __uint_as_float(p1));
            }
            rs += __shfl_xor_sync(0xffffffffu, rs, 1);
            rs += __shfl_xor_sync(0xffffffffu, rs, 2);
            l[rh] = l[rh] * fs + rs;
            m[rh] = mn;
            #pragma unroll
            for (int nt = 0; nt < 8; nt++) {
                o[nt][2 * rh]     *= fs;
                o[nt][2 * rh + 1] *= fs;
            }
        }
        __syncwarp();

        // O += P @ V
        #pragma unroll
        for (int ks = 0; ks < 8; ks++) {
            const int kk = ks * 8;
            unsigned a0 = __float_as_uint(Ps[(qr + g)     * FS + kk + tg]);
            unsigned a1 = __float_as_uint(Ps[(qr + g + 8) * FS + kk + tg]);
            unsigned a2 = __float_as_uint(Ps[(qr + g)     * FS + kk + tg + 4]);
            unsigned a3 = __float_as_uint(Ps[(qr + g + 8) * FS + kk + tg + 4]);
            #pragma unroll
            for (int nt = 0; nt < 8; nt++) {
                unsigned b0 = __float_as_uint(Vs[(kk + tg)     * FS + nt * 8 + g]);
                unsigned b1 = __float_as_uint(Vs[(kk + tg + 4) * FS + nt * 8 + g]);
                mma_tf32(o[nt][0], o[nt][1], o[nt][2], o[nt][3],
                         a0, a1, a2, a3, b0, b1);
            }
        }
    }

    // epilogue: normalize, tf32-round (feeds gemm2), store
    const float i0 = 1.f / l[0], i1 = 1.f / l[1];
    size_t r0 = (base + qt * 64 + qr + g) * DIMN + h * DHEAD;
    size_t r1 = r0 + 8 * DIMN;
    #pragma unroll
    for (int nt = 0; nt < 8; nt++) {
        int col = nt * 8 + 2 * tg;
        *(float2*)(attn + r0 + col) =
            make_float2(__uint_as_float(f2tf(o[nt][0] * i0)),
                        __uint_as_float(f2tf(o[nt][1] * i0)));
        *(float2*)(attn + r1 + col) =
            make_float2(__uint_as_float(f2tf(o[nt][2] * i1)),
                        __uint_as_float(f2tf(o[nt][3] * i1)));
    }
}

// ---------------------------------------------------------------------------
extern "C" void kernel_launch(void* const* d_in, const int* in_sizes, int n_in,
                              void* d_out, int out_size)
{
    const float* x      = (const float*)d_in[0];
    const float* gamma  = (const float*)d_in[1];
    const float* beta   = (const float*)d_in[2];
    const float* w_qkv  = (const float*)d_in[3];
    const float* w_out  = (const float*)d_in[4];
    const float* b_out  = (const float*)d_in[5];
    float* out = (float*)d_out;

    float *xn, *qkvp, *attnp, *wq, *wo;
    cudaGetSymbolAddress((void**)&xn,    g_xn);
    cudaGetSymbolAddress((void**)&qkvp,  g_qkv);
    cudaGetSymbolAddress((void**)&attnp, g_attn);
    cudaGetSymbolAddress((void**)&wq,    g_wq);
    cudaGetSymbolAddress((void**)&wo,    g_wo);

    const int gemm_smem  = (2 * ABUF + 2 * BBUF) * sizeof(float);   // 71680
    const int flash_smem = 4 * 64 * FS * sizeof(float);             // 69632
    cudaFuncSetAttribute(gemm_tc,  cudaFuncAttributeMaxDynamicSharedMemorySize, gemm_smem);
    cudaFuncSetAttribute(flash_tc, cudaFuncAttributeMaxDynamicSharedMemorySize, flash_smem);

    cvt_kernel<<<(DIMN * QKV_N / 4 + 255) / 256, 256>>>(w_qkv, wq, DIMN * QKV_N / 4);
    cvt_kernel<<<(DIMN * DIMN  / 4 + 255) / 256, 256>>>(w_out, wo, DIMN * DIMN / 4);
    ln_kernel<<<ROWS, 256>>>(x, gamma, beta);
    gemm_tc<<<dim3(QKV_N / 128, ROWS / 128), 256, gemm_smem>>>(xn, wq, nullptr, qkvp,
                                                               ROWS, QKV_N, DIMN);
    flash_tc<<<dim3(SEQ / 64, BATCH * HEADS), 128, flash_smem>>>(qkvp, attnp);
    gemm_tc<<<dim3(DIMN / 128, ROWS / 128), 256, gemm_smem>>>(attnp, wo, b_out, out,
                                                              ROWS, DIMN, DIMN);
}